// round 14
// baseline (speedup 1.0000x reference)
#include <cuda_runtime.h>
#include <math.h>

#define BATCH   2
#define SEQ     2048
#define DIM     1024
#define NHEADS  16
#define DH      64
#define NTOK    (BATCH*SEQ)          // 4096
#define QKVC    (3*NHEADS*DH)        // 3072

// -------- scratch (allocation-free: __device__ globals) --------
__device__ float g_xn  [(size_t)NTOK * DIM];    // tf32-rounded
__device__ float g_qkv [(size_t)NTOK * QKVC];   // q,k tf32-rounded after rope
__device__ float g_vt  [(size_t)BATCH * NHEADS * DH * SEQ];  // V^T, tf32-rounded
__device__ float g_gate[NTOK * NHEADS];
__device__ float g_att [(size_t)NTOK * DIM];    // tf32-rounded
__device__ float g_wqkvt[(size_t)DIM * QKVC];   // tf32-rounded w_qkv
__device__ float g_woutt[(size_t)DIM * DIM];    // tf32-rounded w_out

// ---------- tf32 / mma / cp.async / ldmatrix helpers ----------
__device__ __forceinline__ float tf32r(float x) {
    unsigned u; asm("cvt.rna.tf32.f32 %0, %1;" : "=r"(u) : "f"(x));
    return __uint_as_float(u);
}
__device__ __forceinline__ void mma_tf32(float* d, const unsigned* a,
                                         unsigned b0, unsigned b1) {
    asm volatile("mma.sync.aligned.m16n8k8.row.col.f32.tf32.tf32.f32 "
        "{%0,%1,%2,%3}, {%4,%5,%6,%7}, {%8,%9}, {%0,%1,%2,%3};"
        : "+f"(d[0]), "+f"(d[1]), "+f"(d[2]), "+f"(d[3])
        : "r"(a[0]), "r"(a[1]), "r"(a[2]), "r"(a[3]), "r"(b0), "r"(b1));
}
__device__ __forceinline__ unsigned f2u(float x) { return __float_as_uint(x); }

__device__ __forceinline__ void ldsm4(unsigned& r0, unsigned& r1,
                                      unsigned& r2, unsigned& r3, const void* p) {
    unsigned a = (unsigned)__cvta_generic_to_shared(p);
    asm volatile("ldmatrix.sync.aligned.m8n8.x4.shared.b16 {%0,%1,%2,%3}, [%4];"
        : "=r"(r0), "=r"(r1), "=r"(r2), "=r"(r3) : "r"(a));
}

__device__ __forceinline__ void cpa16(void* s, const void* g) {
    unsigned sa = (unsigned)__cvta_generic_to_shared(s);
    asm volatile("cp.async.ca.shared.global [%0], [%1], 16;" :: "r"(sa), "l"(g));
}
#define CP_COMMIT() asm volatile("cp.async.commit_group;")
#define CP_WAIT(n)  asm volatile("cp.async.wait_group %0;" :: "n"(n))

// ============================================================
// 0a) tf32 pre-round (no transpose)
// ============================================================
__global__ __launch_bounds__(256) void round_k(const float* __restrict__ src,
                                               float* __restrict__ dst)
{
    size_t i = (size_t)blockIdx.x * 256 + threadIdx.x;
    float4 v = ((const float4*)src)[i];
    ((float4*)dst)[i] = make_float4(tf32r(v.x), tf32r(v.y), tf32r(v.z), tf32r(v.w));
}

// ============================================================
// 0b) V transpose + round
// ============================================================
__global__ __launch_bounds__(256) void vt_k()
{
    __shared__ float tile[32][33];
    int k0 = blockIdx.x * 32, d0 = blockIdx.y * 32;
    int b = blockIdx.z >> 4, h = blockIdx.z & 15;
    int tx = threadIdx.x & 31, ty = threadIdx.x >> 5;
    #pragma unroll
    for (int i = 0; i < 32; i += 8)
        tile[ty + i][tx] = g_qkv[(size_t)(b * SEQ + k0 + ty + i) * QKVC + 2048 + h * DH + d0 + tx];
    __syncthreads();
    size_t base = ((size_t)blockIdx.z * DH + d0) * SEQ + k0;
    #pragma unroll
    for (int i = 0; i < 32; i += 8)
        g_vt[base + (size_t)(ty + i) * SEQ + tx] = tf32r(tile[tx][ty + i]);
}

// ============================================================
// 1) RMSNorm variant (tf32-rounded output)
// ============================================================
__global__ __launch_bounds__(256) void rmsnorm_k(const float* __restrict__ x,
                                                 const float* __restrict__ gamma)
{
    int t = blockIdx.x;
    const float4* xr = (const float4*)(x + (size_t)t * DIM);
    float4 a = xr[threadIdx.x];
    float ss = a.x*a.x + a.y*a.y + a.z*a.z + a.w*a.w;

    __shared__ float red[8];
    #pragma unroll
    for (int o = 16; o; o >>= 1) ss += __shfl_xor_sync(0xFFFFFFFFu, ss, o);
    if ((threadIdx.x & 31) == 0) red[threadIdx.x >> 5] = ss;
    __syncthreads();
    if (threadIdx.x < 32) {
        float s2 = (threadIdx.x < 8) ? red[threadIdx.x] : 0.0f;
        #pragma unroll
        for (int o = 4; o; o >>= 1) s2 += __shfl_xor_sync(0xFFFFFFFFu, s2, o);
        if (threadIdx.x == 0) red[0] = s2;
    }
    __syncthreads();
    float inv = rsqrtf(red[0]) * 32.0f;
    const float4* g4 = (const float4*)gamma;
    float4 g = g4[threadIdx.x];
    float4 o4 = make_float4(tf32r(a.x*inv*g.x), tf32r(a.y*inv*g.y),
                            tf32r(a.z*inv*g.z), tf32r(a.w*inv*g.w));
    ((float4*)(g_xn + (size_t)t * DIM))[threadIdx.x] = o4;
}

// ============================================================
// 2) TF32 GEMM: BM=128 BN=64 BK=16, 256 thr = 8 warps (4m x 2n),
//    warp tile 32x32, 3 CTAs/SM target. LDSM A, scalar B,
//    cp.async double buffer, one sync per tile.
// ============================================================
__global__ __launch_bounds__(256, 3) void tgemm_k(const float* __restrict__ A,
                                                  const float* __restrict__ Bm,
                                                  float* __restrict__ C,
                                                  int M, int Nn, int K)
{
    __shared__ float As[2][128][20];
    __shared__ float Bs[2][16][72];

    int tid = threadIdx.x;
    int warp = tid >> 5, lane = tid & 31;
    int g = lane >> 2, tig = lane & 3;
    int wm = (warp >> 1) * 32;     // 4 warps down M
    int wn = (warp & 1) * 32;      // 2 warps across N

    int lrowA = lane & 15;
    int lcolA = (lane >> 4) << 2;

    int ar = tid >> 2;             // 0..63 (rows ar, ar+64)
    int ac = (tid & 3) * 4;
    int br = tid >> 4;             // 0..15
    int bc = (tid & 15) * 4;       // 0..60

    const float* Aq  = A + (size_t)(blockIdx.y * 128 + ar) * K + ac;
    const float* Aq2 = Aq + (size_t)64 * K;
    const float* Bq  = Bm + (size_t)br * Nn + blockIdx.x * 64 + bc;

    float acc[2][4][4];
    #pragma unroll
    for (int i = 0; i < 2; i++)
        #pragma unroll
        for (int j = 0; j < 4; j++)
            #pragma unroll
            for (int r = 0; r < 4; r++) acc[i][j][r] = 0.0f;

    cpa16(&As[0][ar][ac],      Aq);
    cpa16(&As[0][ar + 64][ac], Aq2);
    cpa16(&Bs[0][br][bc],      Bq);
    CP_COMMIT();

    int T = K / 16;
    for (int t = 0; t < T; t++) {
        int cur = t & 1;
        CP_WAIT(0);
        __syncthreads();

        if (t + 1 < T) {
            Aq += 16; Aq2 += 16; Bq += (size_t)16 * Nn;
            int nxt = cur ^ 1;
            cpa16(&As[nxt][ar][ac],      Aq);
            cpa16(&As[nxt][ar + 64][ac], Aq2);
            cpa16(&Bs[nxt][br][bc],      Bq);
            CP_COMMIT();
        }

        #pragma unroll
        for (int ks = 0; ks < 2; ks++) {
            int k0 = ks * 8;
            unsigned af[2][4], bf[4][2];
            #pragma unroll
            for (int mt = 0; mt < 2; mt++)
                ldsm4(af[mt][0], af[mt][1], af[mt][2], af[mt][3],
                      &As[cur][wm + mt * 16 + lrowA][k0 + lcolA]);
            #pragma unroll
            for (int nt = 0; nt < 4; nt++) {
                int cb = wn + nt * 8 + g;
                bf[nt][0] = f2u(Bs[cur][k0 + tig    ][cb]);
                bf[nt][1] = f2u(Bs[cur][k0 + tig + 4][cb]);
            }
            #pragma unroll
            for (int mt = 0; mt < 2; mt++)
                #pragma unroll
                for (int nt = 0; nt < 4; nt++)
                    mma_tf32(acc[mt][nt], af[mt], bf[nt][0], bf[nt][1]);
        }
    }

    int m0 = blockIdx.y * 128 + wm, n0 = blockIdx.x * 64 + wn;
    #pragma unroll
    for (int mt = 0; mt < 2; mt++) {
        int row = m0 + mt * 16 + g;
        #pragma unroll
        for (int nt = 0; nt < 4; nt++) {
            int col = n0 + nt * 8 + 2 * tig;
            *(float2*)&C[(size_t)row * Nn + col]       = make_float2(acc[mt][nt][0], acc[mt][nt][1]);
            *(float2*)&C[(size_t)(row + 8) * Nn + col] = make_float2(acc[mt][nt][2], acc[mt][nt][3]);
        }
    }
}

// ============================================================
// 3) Gates
// ============================================================
__global__ __launch_bounds__(256) void gates_k(const float* __restrict__ wg,
                                               const float* __restrict__ bg)
{
    int t = blockIdx.x;
    int tid = threadIdx.x;
    int h = tid & 15, chunk = tid >> 4;
    const float* xr = g_xn + (size_t)t * DIM;
    float acc = 0.0f;
    int d0 = chunk * 64;
    #pragma unroll 8
    for (int d = d0; d < d0 + 64; d++) acc += xr[d] * wg[d * NHEADS + h];

    __shared__ float s[16][16];
    s[chunk][h] = acc;
    __syncthreads();
    if (tid < 16) {
        float v = bg[tid];
        #pragma unroll
        for (int c = 0; c < 16; c++) v += s[c][tid];
        g_gate[t * NHEADS + tid] = 1.0f / (1.0f + expf(-v));
    }
}

// ============================================================
// 4) RoPE (interleaved), writes tf32-rounded q,k
// ============================================================
__global__ __launch_bounds__(256) void rope_k(const float* __restrict__ freqs)
{
    int t = blockIdx.x;
    int pos = t & (SEQ - 1);
    for (int p = threadIdx.x; p < 1024; p += 256) {
        int mat = p >> 9;
        int rem = p & 511;
        int h = rem >> 5;
        int i = rem & 31;
        float f = (float)pos * freqs[i];
        float sn, cs;
        sincosf(f, &sn, &cs);
        float2* ptr = (float2*)(g_qkv + (size_t)t * QKVC + mat * 1024 + h * DH + 2 * i);
        float2 v = *ptr;
        *ptr = make_float2(tf32r(v.x * cs - v.y * sn), tf32r(v.y * cs + v.x * sn));
    }
}

// ============================================================
// 5) Flash attention tf32 MMA (R12 — best measured).
// ============================================================
#define KSP 76
#define VTP 68
#define KBUF (64 * KSP)
#define VBUF (64 * VTP)
#define VOFF (2 * KBUF)
#define ATTN_SMEM ((2 * KBUF + 2 * VBUF) * 4)
__global__ __launch_bounds__(256) void attn_k()
{
    extern __shared__ float sm[];

    int qt = blockIdx.x, h = blockIdx.y, b = blockIdx.z;
    int tid = threadIdx.x, warp = tid >> 5, lane = tid & 31;
    int g = lane >> 2, tig = lane & 3;
    int tBase = b * SEQ + qt * 128;
    int r0 = warp * 16;
    const float scale = 0.125f;

    int lrowB = (lane & 7) + ((lane & 16) >> 1);
    int lcolB = (lane & 8) >> 1;

    int ldr = tid >> 4;
    int ldc = (tid & 15) << 2;

    const float* Kg = g_qkv + (size_t)(b * SEQ) * QKVC + 1024 + h * DH + ldc;
    const float* Vg = g_vt + ((size_t)(b * NHEADS + h) * DH) * SEQ + ldc;

    unsigned qf[8][4];
    {
        const float* q0 = g_qkv + (size_t)(tBase + r0 + g) * QKVC + h * DH;
        const float* q1 = q0 + (size_t)8 * QKVC;
        #pragma unroll
        for (int k8 = 0; k8 < 8; k8++) {
            int k0 = k8 * 8;
            qf[k8][0] = f2u(q0[k0 + tig]     * scale);
            qf[k8][1] = f2u(q1[k0 + tig]     * scale);
            qf[k8][2] = f2u(q0[k0 + tig + 4] * scale);
            qf[k8][3] = f2u(q1[k0 + tig + 4] * scale);
        }
    }

    float mrow0 = -INFINITY, mrow1 = -INFINITY, lrow0 = 0.0f, lrow1 = 0.0f;
    float o[8][4];
    #pragma unroll
    for (int nt = 0; nt < 8; nt++)
        #pragma unroll
        for (int r = 0; r < 4; r++) o[nt][r] = 0.0f;

    int srcA = (lane & ~3) | (tig >> 1);
    int srcB = srcA + 2;
    bool codd = (tig & 1);

    #pragma unroll
    for (int i = 0; i < 4; i++) {
        int r = ldr + i * 16;
        cpa16(&sm[r * KSP + ldc],        Kg + (size_t)r * QKVC);
        cpa16(&sm[VOFF + r * VTP + ldc], Vg + (size_t)r * SEQ);
    }
    CP_COMMIT();

    int T = SEQ / 64;
    for (int kt = 0; kt < T; kt++) {
        int cur = kt & 1;
        CP_WAIT(0);
        __syncthreads();

        if (kt + 1 < T) {
            int nxt = cur ^ 1;
            const float* Kn = Kg + (size_t)(kt + 1) * 64 * QKVC;
            const float* Vn = Vg + (kt + 1) * 64;
            #pragma unroll
            for (int i = 0; i < 4; i++) {
                int r = ldr + i * 16;
                cpa16(&sm[nxt * KBUF + r * KSP + ldc],        Kn + (size_t)r * QKVC);
                cpa16(&sm[VOFF + nxt * VBUF + r * VTP + ldc], Vn + (size_t)r * SEQ);
            }
            CP_COMMIT();
        }

        const float* Kb = sm + cur * KBUF;
        const float* Vb = sm + VOFF + cur * VBUF;

        float s[8][4];
        #pragma unroll
        for (int nt = 0; nt < 8; nt++)
            #pragma unroll
            for (int r = 0; r < 4; r++) s[nt][r] = 0.0f;

        #pragma unroll
        for (int k8 = 0; k8 < 8; k8++) {
            int k0 = k8 * 8;
            #pragma unroll
            for (int ntp = 0; ntp < 4; ntp++) {
                unsigned b0a, b1a, b0b, b1b;
                ldsm4(b0a, b1a, b0b, b1b, &Kb[(ntp * 16 + lrowB) * KSP + k0 + lcolB]);
                mma_tf32(s[2 * ntp],     qf[k8], b0a, b1a);
                mma_tf32(s[2 * ntp + 1], qf[k8], b0b, b1b);
            }
        }

        float mx0 = -INFINITY, mx1 = -INFINITY;
        #pragma unroll
        for (int nt = 0; nt < 8; nt++) {
            mx0 = fmaxf(mx0, fmaxf(s[nt][0], s[nt][1]));
            mx1 = fmaxf(mx1, fmaxf(s[nt][2], s[nt][3]));
        }
        mx0 = fmaxf(mx0, __shfl_xor_sync(0xFFFFFFFFu, mx0, 1));
        mx0 = fmaxf(mx0, __shfl_xor_sync(0xFFFFFFFFu, mx0, 2));
        mx1 = fmaxf(mx1, __shfl_xor_sync(0xFFFFFFFFu, mx1, 1));
        mx1 = fmaxf(mx1, __shfl_xor_sync(0xFFFFFFFFu, mx1, 2));

        float mn0 = fmaxf(mrow0, mx0), mn1 = fmaxf(mrow1, mx1);
        float corr0 = __expf(mrow0 - mn0), corr1 = __expf(mrow1 - mn1);
        float rs0 = 0.0f, rs1 = 0.0f;
        #pragma unroll
        for (int nt = 0; nt < 8; nt++) {
            s[nt][0] = __expf(s[nt][0] - mn0);
            s[nt][1] = __expf(s[nt][1] - mn0);
            s[nt][2] = __expf(s[nt][2] - mn1);
            s[nt][3] = __expf(s[nt][3] - mn1);
            rs0 += s[nt][0] + s[nt][1];
            rs1 += s[nt][2] + s[nt][3];
        }
        rs0 += __shfl_xor_sync(0xFFFFFFFFu, rs0, 1);
        rs0 += __shfl_xor_sync(0xFFFFFFFFu, rs0, 2);
        rs1 += __shfl_xor_sync(0xFFFFFFFFu, rs1, 1);
        rs1 += __shfl_xor_sync(0xFFFFFFFFu, rs1, 2);
        lrow0 = lrow0 * corr0 + rs0;  mrow0 = mn0;
        lrow1 = lrow1 * corr1 + rs1;  mrow1 = mn1;
        #pragma unroll
        for (int nt = 0; nt < 8; nt++) {
            o[nt][0] *= corr0; o[nt][1] *= corr0;
            o[nt][2] *= corr1; o[nt][3] *= corr1;
        }

        #pragma unroll
        for (int kv = 0; kv < 8; kv++) {
            float e0 = __shfl_sync(0xFFFFFFFFu, s[kv][0], srcA);
            float e1 = __shfl_sync(0xFFFFFFFFu, s[kv][1], srcA);
            float e2 = __shfl_sync(0xFFFFFFFFu, s[kv][2], srcA);
            float e3 = __shfl_sync(0xFFFFFFFFu, s[kv][3], srcA);
            float f0 = __shfl_sync(0xFFFFFFFFu, s[kv][0], srcB);
            float f1 = __shfl_sync(0xFFFFFFFFu, s[kv][1], srcB);
            float f2 = __shfl_sync(0xFFFFFFFFu, s[kv][2], srcB);
            float f3 = __shfl_sync(0xFFFFFFFFu, s[kv][3], srcB);
            unsigned pa[4];
            pa[0] = f2u(tf32r(codd ? e1 : e0));
            pa[1] = f2u(tf32r(codd ? e3 : e2));
            pa[2] = f2u(tf32r(codd ? f1 : f0));
            pa[3] = f2u(tf32r(codd ? f3 : f2));
            #pragma unroll
            for (int ntp = 0; ntp < 4; ntp++) {
                unsigned b0a, b1a, b0b, b1b;
                ldsm4(b0a, b1a, b0b, b1b, &Vb[(ntp * 16 + lrowB) * VTP + kv * 8 + lcolB]);
                mma_tf32(o[2 * ntp],     pa, b0a, b1a);
                mma_tf32(o[2 * ntp + 1], pa, b0b, b1b);
            }
        }
    }

    int row0 = tBase + r0 + g;
    float sc0 = (1.0f / lrow0) * g_gate[row0 * NHEADS + h];
    float sc1 = (1.0f / lrow1) * g_gate[(row0 + 8) * NHEADS + h];
    #pragma unroll
    for (int nt = 0; nt < 8; nt++) {
        int col = h * DH + nt * 8 + 2 * tig;
        *(float2*)&g_att[(size_t)row0 * DIM + col] =
            make_float2(tf32r(o[nt][0] * sc0), tf32r(o[nt][1] * sc0));
        *(float2*)&g_att[(size_t)(row0 + 8) * DIM + col] =
            make_float2(tf32r(o[nt][2] * sc1), tf32r(o[nt][3] * sc1));
    }
}

// ============================================================
// launcher
// ============================================================
extern "C" void kernel_launch(void* const* d_in, const int* in_sizes, int n_in,
                              void* d_out, int out_size)
{
    const float* x       = (const float*)d_in[0];
    const float* gamma   = (const float*)d_in[1];
    const float* w_qkv   = (const float*)d_in[2];
    const float* w_gates = (const float*)d_in[3];
    const float* b_gates = (const float*)d_in[4];
    const float* w_out   = (const float*)d_in[5];
    const float* freqs   = (const float*)d_in[6];
    float* out = (float*)d_out;

    float *xn_p, *qkv_p, *att_p, *wqkvt_p, *woutt_p;
    cudaGetSymbolAddress((void**)&xn_p,    g_xn);
    cudaGetSymbolAddress((void**)&qkv_p,   g_qkv);
    cudaGetSymbolAddress((void**)&att_p,   g_att);
    cudaGetSymbolAddress((void**)&wqkvt_p, g_wqkvt);
    cudaGetSymbolAddress((void**)&woutt_p, g_woutt);

    cudaFuncSetAttribute(attn_k, cudaFuncAttributeMaxDynamicSharedMemorySize, ATTN_SMEM);

    round_k<<<(DIM * QKVC) / 1024, 256>>>(w_qkv, wqkvt_p);
    round_k<<<(DIM * DIM)  / 1024, 256>>>(w_out, woutt_p);
    rmsnorm_k<<<NTOK, 256>>>(x, gamma);
    tgemm_k<<<dim3(QKVC / 64, NTOK / 128), 256>>>(xn_p, wqkvt_p, qkv_p, NTOK, QKVC, DIM);
    gates_k<<<NTOK, 256>>>(w_gates, b_gates);
    rope_k<<<NTOK, 256>>>(freqs);
    vt_k<<<dim3(SEQ / 32, DH / 32, BATCH * NHEADS), 256>>>();
    attn_k<<<dim3(SEQ / 128, NHEADS, BATCH), 256, ATTN_SMEM>>>();
    tgemm_k<<<dim3(DIM / 64, NTOK / 128), 256>>>(att_p, woutt_p, out, NTOK, DIM, DIM);
}

// round 15
// speedup vs baseline: 1.1172x; 1.1172x over previous
#include <cuda_runtime.h>
#include <math.h>

#define BATCH   2
#define SEQ     2048
#define DIM     1024
#define NHEADS  16
#define DH      64
#define NTOK    (BATCH*SEQ)          // 4096
#define QKVC    (3*NHEADS*DH)        // 3072

// -------- scratch (allocation-free: __device__ globals) --------
__device__ float g_xn  [(size_t)NTOK * DIM];    // tf32-rounded
__device__ float g_qkv [(size_t)NTOK * QKVC];   // q,k tf32-rounded (rope fused)
__device__ float g_vt  [(size_t)BATCH * NHEADS * DH * SEQ];  // V^T, tf32-rounded
__device__ float g_gate[NTOK * NHEADS];
__device__ float g_att [(size_t)NTOK * DIM];    // tf32-rounded
__device__ float g_wqkvt[(size_t)DIM * QKVC];   // tf32-rounded w_qkv
__device__ float g_woutt[(size_t)DIM * DIM];    // tf32-rounded w_out

// ---------- tf32 / mma / cp.async / ldmatrix helpers ----------
__device__ __forceinline__ float tf32r(float x) {
    unsigned u; asm("cvt.rna.tf32.f32 %0, %1;" : "=r"(u) : "f"(x));
    return __uint_as_float(u);
}
__device__ __forceinline__ void mma_tf32(float* d, const unsigned* a,
                                         unsigned b0, unsigned b1) {
    asm volatile("mma.sync.aligned.m16n8k8.row.col.f32.tf32.tf32.f32 "
        "{%0,%1,%2,%3}, {%4,%5,%6,%7}, {%8,%9}, {%0,%1,%2,%3};"
        : "+f"(d[0]), "+f"(d[1]), "+f"(d[2]), "+f"(d[3])
        : "r"(a[0]), "r"(a[1]), "r"(a[2]), "r"(a[3]), "r"(b0), "r"(b1));
}
__device__ __forceinline__ unsigned f2u(float x) { return __float_as_uint(x); }

__device__ __forceinline__ void ldsm4(unsigned& r0, unsigned& r1,
                                      unsigned& r2, unsigned& r3, const void* p) {
    unsigned a = (unsigned)__cvta_generic_to_shared(p);
    asm volatile("ldmatrix.sync.aligned.m8n8.x4.shared.b16 {%0,%1,%2,%3}, [%4];"
        : "=r"(r0), "=r"(r1), "=r"(r2), "=r"(r3) : "r"(a));
}

__device__ __forceinline__ void cpa16(void* s, const void* g) {
    unsigned sa = (unsigned)__cvta_generic_to_shared(s);
    asm volatile("cp.async.ca.shared.global [%0], [%1], 16;" :: "r"(sa), "l"(g));
}
#define CP_COMMIT() asm volatile("cp.async.commit_group;")
#define CP_WAIT(n)  asm volatile("cp.async.wait_group %0;" :: "n"(n))

// ============================================================
// 0) tf32 pre-round
// ============================================================
__global__ __launch_bounds__(256) void round_k(const float* __restrict__ src,
                                               float* __restrict__ dst)
{
    size_t i = (size_t)blockIdx.x * 256 + threadIdx.x;
    float4 v = ((const float4*)src)[i];
    ((float4*)dst)[i] = make_float4(tf32r(v.x), tf32r(v.y), tf32r(v.z), tf32r(v.w));
}

// ============================================================
// 1) RMSNorm variant (tf32-rounded output)
// ============================================================
__global__ __launch_bounds__(256) void rmsnorm_k(const float* __restrict__ x,
                                                 const float* __restrict__ gamma)
{
    int t = blockIdx.x;
    const float4* xr = (const float4*)(x + (size_t)t * DIM);
    float4 a = xr[threadIdx.x];
    float ss = a.x*a.x + a.y*a.y + a.z*a.z + a.w*a.w;

    __shared__ float red[8];
    #pragma unroll
    for (int o = 16; o; o >>= 1) ss += __shfl_xor_sync(0xFFFFFFFFu, ss, o);
    if ((threadIdx.x & 31) == 0) red[threadIdx.x >> 5] = ss;
    __syncthreads();
    if (threadIdx.x < 32) {
        float s2 = (threadIdx.x < 8) ? red[threadIdx.x] : 0.0f;
        #pragma unroll
        for (int o = 4; o; o >>= 1) s2 += __shfl_xor_sync(0xFFFFFFFFu, s2, o);
        if (threadIdx.x == 0) red[0] = s2;
    }
    __syncthreads();
    float inv = rsqrtf(red[0]) * 32.0f;
    const float4* g4 = (const float4*)gamma;
    float4 g = g4[threadIdx.x];
    float4 o4 = make_float4(tf32r(a.x*inv*g.x), tf32r(a.y*inv*g.y),
                            tf32r(a.z*inv*g.z), tf32r(a.w*inv*g.w));
    ((float4*)(g_xn + (size_t)t * DIM))[threadIdx.x] = o4;
}

// ============================================================
// 2) TF32 GEMM (R12 hot loop). mode=1: QKV — fused RoPE on q/k
//    (tf32-rounded store) and V written transposed to g_vt.
//    mode=0: plain fp32 store (out-projection).
// ============================================================
__global__ __launch_bounds__(256) void tgemm_k(const float* __restrict__ A,
                                               const float* __restrict__ Bm,
                                               float* __restrict__ C,
                                               int M, int Nn, int K,
                                               const float* __restrict__ freqs,
                                               int mode)
{
    __shared__ float As[2][128][20];
    __shared__ float Bs[2][16][136];

    int tid = threadIdx.x;
    int warp = tid >> 5, lane = tid & 31;
    int g = lane >> 2, tig = lane & 3;
    int wm = (warp >> 2) * 64;
    int wn = (warp & 3) * 32;

    int lrowA = lane & 15;
    int lcolA = (lane >> 4) << 2;

    int ar = tid >> 2;
    int ac = (tid & 3) * 4;
    int br = tid >> 4;
    int bc = (tid & 15) * 8;

    const float* Aq  = A + (size_t)(blockIdx.y * 128 + ar) * K + ac;
    const float* Aq2 = Aq + (size_t)64 * K;
    const float* Bq  = Bm + (size_t)br * Nn + blockIdx.x * 128 + bc;

    float acc[4][4][4];
    #pragma unroll
    for (int i = 0; i < 4; i++)
        #pragma unroll
        for (int j = 0; j < 4; j++)
            #pragma unroll
            for (int r = 0; r < 4; r++) acc[i][j][r] = 0.0f;

    cpa16(&As[0][ar][ac],      Aq);
    cpa16(&As[0][ar + 64][ac], Aq2);
    cpa16(&Bs[0][br][bc],      Bq);
    cpa16(&Bs[0][br][bc + 4],  Bq + 4);
    CP_COMMIT();

    int T = K / 16;
    for (int t = 0; t < T; t++) {
        int cur = t & 1;
        CP_WAIT(0);
        __syncthreads();

        if (t + 1 < T) {
            Aq += 16; Aq2 += 16; Bq += (size_t)16 * Nn;
            int nxt = cur ^ 1;
            cpa16(&As[nxt][ar][ac],      Aq);
            cpa16(&As[nxt][ar + 64][ac], Aq2);
            cpa16(&Bs[nxt][br][bc],      Bq);
            cpa16(&Bs[nxt][br][bc + 4],  Bq + 4);
            CP_COMMIT();
        }

        #pragma unroll
        for (int ks = 0; ks < 2; ks++) {
            int k0 = ks * 8;
            unsigned af[4][4], bf[4][2];
            #pragma unroll
            for (int mt = 0; mt < 4; mt++)
                ldsm4(af[mt][0], af[mt][1], af[mt][2], af[mt][3],
                      &As[cur][wm + mt * 16 + lrowA][k0 + lcolA]);
            #pragma unroll
            for (int nt = 0; nt < 4; nt++) {
                int cb = wn + nt * 8 + g;
                bf[nt][0] = f2u(Bs[cur][k0 + tig    ][cb]);
                bf[nt][1] = f2u(Bs[cur][k0 + tig + 4][cb]);
            }
            #pragma unroll
            for (int mt = 0; mt < 4; mt++)
                #pragma unroll
                for (int nt = 0; nt < 4; nt++)
                    mma_tf32(acc[mt][nt], af[mt], bf[nt][0], bf[nt][1]);
        }
    }

    int m0 = blockIdx.y * 128 + wm, n0 = blockIdx.x * 128 + wn;
    if (mode == 0) {
        #pragma unroll
        for (int mt = 0; mt < 4; mt++) {
            int row = m0 + mt * 16 + g;
            #pragma unroll
            for (int nt = 0; nt < 4; nt++) {
                int col = n0 + nt * 8 + 2 * tig;
                *(float2*)&C[(size_t)row * Nn + col]       = make_float2(acc[mt][nt][0], acc[mt][nt][1]);
                *(float2*)&C[(size_t)(row + 8) * Nn + col] = make_float2(acc[mt][nt][2], acc[mt][nt][3]);
            }
        }
    } else {
        // QKV epilogue: rope on q/k planes (col<2048), V -> g_vt transposed
        #pragma unroll
        for (int mt = 0; mt < 4; mt++) {
            #pragma unroll
            for (int nt = 0; nt < 4; nt++) {
                int col = n0 + nt * 8 + 2 * tig;
                #pragma unroll
                for (int half = 0; half < 2; half++) {
                    int row = m0 + mt * 16 + g + half * 8;
                    float vx = acc[mt][nt][half * 2];
                    float vy = acc[mt][nt][half * 2 + 1];
                    if (col < 2048) {
                        int i = (col & 63) >> 1;
                        int pos = row & (SEQ - 1);
                        float f = (float)pos * freqs[i];
                        float sn, cs;
                        sincosf(f, &sn, &cs);
                        *(float2*)&C[(size_t)row * Nn + col] =
                            make_float2(tf32r(vx * cs - vy * sn),
                                        tf32r(vy * cs + vx * sn));
                    } else {
                        int hh = (col >> 6) & 15;
                        int d = col & 63;
                        int bb = row >> 11;
                        int key = row & (SEQ - 1);
                        size_t base = ((size_t)(bb * NHEADS + hh) * DH + d) * SEQ + key;
                        g_vt[base]       = tf32r(vx);
                        g_vt[base + SEQ] = tf32r(vy);
                    }
                }
            }
        }
    }
}

// ============================================================
// 3) Gates
// ============================================================
__global__ __launch_bounds__(256) void gates_k(const float* __restrict__ wg,
                                               const float* __restrict__ bg)
{
    int t = blockIdx.x;
    int tid = threadIdx.x;
    int h = tid & 15, chunk = tid >> 4;
    const float* xr = g_xn + (size_t)t * DIM;
    float acc = 0.0f;
    int d0 = chunk * 64;
    #pragma unroll 8
    for (int d = d0; d < d0 + 64; d++) acc += xr[d] * wg[d * NHEADS + h];

    __shared__ float s[16][16];
    s[chunk][h] = acc;
    __syncthreads();
    if (tid < 16) {
        float v = bg[tid];
        #pragma unroll
        for (int c = 0; c < 16; c++) v += s[c][tid];
        g_gate[t * NHEADS + tid] = 1.0f / (1.0f + expf(-v));
    }
}

// ============================================================
// 5) Flash attention tf32 MMA (R12 — best measured).
// ============================================================
#define KSP 76
#define VTP 68
#define KBUF (64 * KSP)
#define VBUF (64 * VTP)
#define VOFF (2 * KBUF)
#define ATTN_SMEM ((2 * KBUF + 2 * VBUF) * 4)
__global__ __launch_bounds__(256) void attn_k()
{
    extern __shared__ float sm[];

    int qt = blockIdx.x, h = blockIdx.y, b = blockIdx.z;
    int tid = threadIdx.x, warp = tid >> 5, lane = tid & 31;
    int g = lane >> 2, tig = lane & 3;
    int tBase = b * SEQ + qt * 128;
    int r0 = warp * 16;
    const float scale = 0.125f;

    int lrowB = (lane & 7) + ((lane & 16) >> 1);
    int lcolB = (lane & 8) >> 1;

    int ldr = tid >> 4;
    int ldc = (tid & 15) << 2;

    const float* Kg = g_qkv + (size_t)(b * SEQ) * QKVC + 1024 + h * DH + ldc;
    const float* Vg = g_vt + ((size_t)(b * NHEADS + h) * DH) * SEQ + ldc;

    unsigned qf[8][4];
    {
        const float* q0 = g_qkv + (size_t)(tBase + r0 + g) * QKVC + h * DH;
        const float* q1 = q0 + (size_t)8 * QKVC;
        #pragma unroll
        for (int k8 = 0; k8 < 8; k8++) {
            int k0 = k8 * 8;
            qf[k8][0] = f2u(q0[k0 + tig]     * scale);
            qf[k8][1] = f2u(q1[k0 + tig]     * scale);
            qf[k8][2] = f2u(q0[k0 + tig + 4] * scale);
            qf[k8][3] = f2u(q1[k0 + tig + 4] * scale);
        }
    }

    float mrow0 = -INFINITY, mrow1 = -INFINITY, lrow0 = 0.0f, lrow1 = 0.0f;
    float o[8][4];
    #pragma unroll
    for (int nt = 0; nt < 8; nt++)
        #pragma unroll
        for (int r = 0; r < 4; r++) o[nt][r] = 0.0f;

    int srcA = (lane & ~3) | (tig >> 1);
    int srcB = srcA + 2;
    bool codd = (tig & 1);

    #pragma unroll
    for (int i = 0; i < 4; i++) {
        int r = ldr + i * 16;
        cpa16(&sm[r * KSP + ldc],        Kg + (size_t)r * QKVC);
        cpa16(&sm[VOFF + r * VTP + ldc], Vg + (size_t)r * SEQ);
    }
    CP_COMMIT();

    int T = SEQ / 64;
    for (int kt = 0; kt < T; kt++) {
        int cur = kt & 1;
        CP_WAIT(0);
        __syncthreads();

        if (kt + 1 < T) {
            int nxt = cur ^ 1;
            const float* Kn = Kg + (size_t)(kt + 1) * 64 * QKVC;
            const float* Vn = Vg + (kt + 1) * 64;
            #pragma unroll
            for (int i = 0; i < 4; i++) {
                int r = ldr + i * 16;
                cpa16(&sm[nxt * KBUF + r * KSP + ldc],        Kn + (size_t)r * QKVC);
                cpa16(&sm[VOFF + nxt * VBUF + r * VTP + ldc], Vn + (size_t)r * SEQ);
            }
            CP_COMMIT();
        }

        const float* Kb = sm + cur * KBUF;
        const float* Vb = sm + VOFF + cur * VBUF;

        float s[8][4];
        #pragma unroll
        for (int nt = 0; nt < 8; nt++)
            #pragma unroll
            for (int r = 0; r < 4; r++) s[nt][r] = 0.0f;

        #pragma unroll
        for (int k8 = 0; k8 < 8; k8++) {
            int k0 = k8 * 8;
            #pragma unroll
            for (int ntp = 0; ntp < 4; ntp++) {
                unsigned b0a, b1a, b0b, b1b;
                ldsm4(b0a, b1a, b0b, b1b, &Kb[(ntp * 16 + lrowB) * KSP + k0 + lcolB]);
                mma_tf32(s[2 * ntp],     qf[k8], b0a, b1a);
                mma_tf32(s[2 * ntp + 1], qf[k8], b0b, b1b);
            }
        }

        float mx0 = -INFINITY, mx1 = -INFINITY;
        #pragma unroll
        for (int nt = 0; nt < 8; nt++) {
            mx0 = fmaxf(mx0, fmaxf(s[nt][0], s[nt][1]));
            mx1 = fmaxf(mx1, fmaxf(s[nt][2], s[nt][3]));
        }
        mx0 = fmaxf(mx0, __shfl_xor_sync(0xFFFFFFFFu, mx0, 1));
        mx0 = fmaxf(mx0, __shfl_xor_sync(0xFFFFFFFFu, mx0, 2));
        mx1 = fmaxf(mx1, __shfl_xor_sync(0xFFFFFFFFu, mx1, 1));
        mx1 = fmaxf(mx1, __shfl_xor_sync(0xFFFFFFFFu, mx1, 2));

        float mn0 = fmaxf(mrow0, mx0), mn1 = fmaxf(mrow1, mx1);
        float corr0 = __expf(mrow0 - mn0), corr1 = __expf(mrow1 - mn1);
        float rs0 = 0.0f, rs1 = 0.0f;
        #pragma unroll
        for (int nt = 0; nt < 8; nt++) {
            s[nt][0] = __expf(s[nt][0] - mn0);
            s[nt][1] = __expf(s[nt][1] - mn0);
            s[nt][2] = __expf(s[nt][2] - mn1);
            s[nt][3] = __expf(s[nt][3] - mn1);
            rs0 += s[nt][0] + s[nt][1];
            rs1 += s[nt][2] + s[nt][3];
        }
        rs0 += __shfl_xor_sync(0xFFFFFFFFu, rs0, 1);
        rs0 += __shfl_xor_sync(0xFFFFFFFFu, rs0, 2);
        rs1 += __shfl_xor_sync(0xFFFFFFFFu, rs1, 1);
        rs1 += __shfl_xor_sync(0xFFFFFFFFu, rs1, 2);
        lrow0 = lrow0 * corr0 + rs0;  mrow0 = mn0;
        lrow1 = lrow1 * corr1 + rs1;  mrow1 = mn1;
        #pragma unroll
        for (int nt = 0; nt < 8; nt++) {
            o[nt][0] *= corr0; o[nt][1] *= corr0;
            o[nt][2] *= corr1; o[nt][3] *= corr1;
        }

        #pragma unroll
        for (int kv = 0; kv < 8; kv++) {
            float e0 = __shfl_sync(0xFFFFFFFFu, s[kv][0], srcA);
            float e1 = __shfl_sync(0xFFFFFFFFu, s[kv][1], srcA);
            float e2 = __shfl_sync(0xFFFFFFFFu, s[kv][2], srcA);
            float e3 = __shfl_sync(0xFFFFFFFFu, s[kv][3], srcA);
            float f0 = __shfl_sync(0xFFFFFFFFu, s[kv][0], srcB);
            float f1 = __shfl_sync(0xFFFFFFFFu, s[kv][1], srcB);
            float f2 = __shfl_sync(0xFFFFFFFFu, s[kv][2], srcB);
            float f3 = __shfl_sync(0xFFFFFFFFu, s[kv][3], srcB);
            unsigned pa[4];
            pa[0] = f2u(tf32r(codd ? e1 : e0));
            pa[1] = f2u(tf32r(codd ? e3 : e2));
            pa[2] = f2u(tf32r(codd ? f1 : f0));
            pa[3] = f2u(tf32r(codd ? f3 : f2));
            #pragma unroll
            for (int ntp = 0; ntp < 4; ntp++) {
                unsigned b0a, b1a, b0b, b1b;
                ldsm4(b0a, b1a, b0b, b1b, &Vb[(ntp * 16 + lrowB) * VTP + kv * 8 + lcolB]);
                mma_tf32(o[2 * ntp],     pa, b0a, b1a);
                mma_tf32(o[2 * ntp + 1], pa, b0b, b1b);
            }
        }
    }

    int row0 = tBase + r0 + g;
    float sc0 = (1.0f / lrow0) * g_gate[row0 * NHEADS + h];
    float sc1 = (1.0f / lrow1) * g_gate[(row0 + 8) * NHEADS + h];
    #pragma unroll
    for (int nt = 0; nt < 8; nt++) {
        int col = h * DH + nt * 8 + 2 * tig;
        *(float2*)&g_att[(size_t)row0 * DIM + col] =
            make_float2(tf32r(o[nt][0] * sc0), tf32r(o[nt][1] * sc0));
        *(float2*)&g_att[(size_t)(row0 + 8) * DIM + col] =
            make_float2(tf32r(o[nt][2] * sc1), tf32r(o[nt][3] * sc1));
    }
}

// ============================================================
// launcher — two-stream DAG (fork/join via events, capture-legal)
// ============================================================
extern "C" void kernel_launch(void* const* d_in, const int* in_sizes, int n_in,
                              void* d_out, int out_size)
{
    const float* x       = (const float*)d_in[0];
    const float* gamma   = (const float*)d_in[1];
    const float* w_qkv   = (const float*)d_in[2];
    const float* w_gates = (const float*)d_in[3];
    const float* b_gates = (const float*)d_in[4];
    const float* w_out   = (const float*)d_in[5];
    const float* freqs   = (const float*)d_in[6];
    float* out = (float*)d_out;

    float *xn_p, *qkv_p, *att_p, *wqkvt_p, *woutt_p;
    cudaGetSymbolAddress((void**)&xn_p,    g_xn);
    cudaGetSymbolAddress((void**)&qkv_p,   g_qkv);
    cudaGetSymbolAddress((void**)&att_p,   g_att);
    cudaGetSymbolAddress((void**)&wqkvt_p, g_wqkvt);
    cudaGetSymbolAddress((void**)&woutt_p, g_woutt);

    cudaFuncSetAttribute(attn_k, cudaFuncAttributeMaxDynamicSharedMemorySize, ATTN_SMEM);

    static cudaStream_t s2 = nullptr;
    static cudaEvent_t e0 = nullptr, eR = nullptr, eX = nullptr, eG = nullptr;
    if (!s2) {
        cudaStreamCreateWithFlags(&s2, cudaStreamNonBlocking);
        cudaEventCreateWithFlags(&e0, cudaEventDisableTiming);
        cudaEventCreateWithFlags(&eR, cudaEventDisableTiming);
        cudaEventCreateWithFlags(&eX, cudaEventDisableTiming);
        cudaEventCreateWithFlags(&eG, cudaEventDisableTiming);
    }

    // fork: weight pre-rounds on s2, rmsnorm on main
    cudaEventRecord(e0, 0);
    cudaStreamWaitEvent(s2, e0, 0);
    round_k<<<(DIM * QKVC) / 1024, 256, 0, s2>>>(w_qkv, wqkvt_p);
    round_k<<<(DIM * DIM)  / 1024, 256, 0, s2>>>(w_out, woutt_p);
    cudaEventRecord(eR, s2);

    rmsnorm_k<<<NTOK, 256>>>(x, gamma);
    cudaEventRecord(eX, 0);

    // gates on s2 (needs xn), concurrent with QKV GEMM on main
    cudaStreamWaitEvent(s2, eX, 0);
    gates_k<<<NTOK, 256, 0, s2>>>(w_gates, b_gates);
    cudaEventRecord(eG, s2);

    // main: QKV GEMM (needs rounded weights) with fused rope + V^T
    cudaStreamWaitEvent(0, eR, 0);
    tgemm_k<<<dim3(QKVC / 128, NTOK / 128), 256>>>(xn_p, wqkvt_p, qkv_p,
                                                   NTOK, QKVC, DIM, freqs, 1);

    // join gates before attention
    cudaStreamWaitEvent(0, eG, 0);
    attn_k<<<dim3(SEQ / 128, NHEADS, BATCH), 256, ATTN_SMEM>>>();
    tgemm_k<<<dim3(DIM / 128, NTOK / 128), 256>>>(att_p, woutt_p, out,
                                                  NTOK, DIM, DIM, freqs, 0);
}

// round 16
// speedup vs baseline: 1.1519x; 1.0311x over previous
#include <cuda_runtime.h>
#include <math.h>

#define BATCH   2
#define SEQ     2048
#define DIM     1024
#define NHEADS  16
#define DH      64
#define NTOK    (BATCH*SEQ)          // 4096
#define QKVC    (3*NHEADS*DH)        // 3072

// -------- scratch (allocation-free: __device__ globals) --------
__device__ float g_xn  [(size_t)NTOK * DIM];    // tf32-rounded
__device__ float g_qkv [(size_t)NTOK * QKVC];   // q,k tf32-rounded (rope fused)
__device__ float g_vt  [(size_t)BATCH * NHEADS * DH * SEQ];  // V^T, tf32-rounded
__device__ float g_gate[NTOK * NHEADS];
__device__ float g_att [(size_t)NTOK * DIM];    // tf32-rounded
__device__ float g_wqkvt[(size_t)DIM * QKVC];   // tf32-rounded w_qkv
__device__ float g_woutt[(size_t)DIM * DIM];    // tf32-rounded w_out

// ---------- tf32 / mma / cp.async / ldmatrix helpers ----------
__device__ __forceinline__ float tf32r(float x) {
    unsigned u; asm("cvt.rna.tf32.f32 %0, %1;" : "=r"(u) : "f"(x));
    return __uint_as_float(u);
}
__device__ __forceinline__ void mma_tf32(float* d, const unsigned* a,
                                         unsigned b0, unsigned b1) {
    asm volatile("mma.sync.aligned.m16n8k8.row.col.f32.tf32.tf32.f32 "
        "{%0,%1,%2,%3}, {%4,%5,%6,%7}, {%8,%9}, {%0,%1,%2,%3};"
        : "+f"(d[0]), "+f"(d[1]), "+f"(d[2]), "+f"(d[3])
        : "r"(a[0]), "r"(a[1]), "r"(a[2]), "r"(a[3]), "r"(b0), "r"(b1));
}
__device__ __forceinline__ unsigned f2u(float x) { return __float_as_uint(x); }

__device__ __forceinline__ void ldsm4(unsigned& r0, unsigned& r1,
                                      unsigned& r2, unsigned& r3, const void* p) {
    unsigned a = (unsigned)__cvta_generic_to_shared(p);
    asm volatile("ldmatrix.sync.aligned.m8n8.x4.shared.b16 {%0,%1,%2,%3}, [%4];"
        : "=r"(r0), "=r"(r1), "=r"(r2), "=r"(r3) : "r"(a));
}

__device__ __forceinline__ void cpa16(void* s, const void* g) {
    unsigned sa = (unsigned)__cvta_generic_to_shared(s);
    asm volatile("cp.async.ca.shared.global [%0], [%1], 16;" :: "r"(sa), "l"(g));
}
#define CP_COMMIT() asm volatile("cp.async.commit_group;")
#define CP_WAIT(n)  asm volatile("cp.async.wait_group %0;" :: "n"(n))

// ============================================================
// 0) tf32 pre-round
// ============================================================
__global__ __launch_bounds__(256) void round_k(const float* __restrict__ src,
                                               float* __restrict__ dst)
{
    size_t i = (size_t)blockIdx.x * 256 + threadIdx.x;
    float4 v = ((const float4*)src)[i];
    ((float4*)dst)[i] = make_float4(tf32r(v.x), tf32r(v.y), tf32r(v.z), tf32r(v.w));
}

// ============================================================
// 1) RMSNorm variant (tf32-rounded output)
// ============================================================
__global__ __launch_bounds__(256) void rmsnorm_k(const float* __restrict__ x,
                                                 const float* __restrict__ gamma)
{
    int t = blockIdx.x;
    const float4* xr = (const float4*)(x + (size_t)t * DIM);
    float4 a = xr[threadIdx.x];
    float ss = a.x*a.x + a.y*a.y + a.z*a.z + a.w*a.w;

    __shared__ float red[8];
    #pragma unroll
    for (int o = 16; o; o >>= 1) ss += __shfl_xor_sync(0xFFFFFFFFu, ss, o);
    if ((threadIdx.x & 31) == 0) red[threadIdx.x >> 5] = ss;
    __syncthreads();
    if (threadIdx.x < 32) {
        float s2 = (threadIdx.x < 8) ? red[threadIdx.x] : 0.0f;
        #pragma unroll
        for (int o = 4; o; o >>= 1) s2 += __shfl_xor_sync(0xFFFFFFFFu, s2, o);
        if (threadIdx.x == 0) red[0] = s2;
    }
    __syncthreads();
    float inv = rsqrtf(red[0]) * 32.0f;
    const float4* g4 = (const float4*)gamma;
    float4 g = g4[threadIdx.x];
    float4 o4 = make_float4(tf32r(a.x*inv*g.x), tf32r(a.y*inv*g.y),
                            tf32r(a.z*inv*g.z), tf32r(a.w*inv*g.w));
    ((float4*)(g_xn + (size_t)t * DIM))[threadIdx.x] = o4;
}

// ============================================================
// 2) TF32 GEMM (R12 hot loop). mode=1: QKV — fused RoPE on q/k
//    and V written transposed to g_vt. mode=0: plain store.
// ============================================================
__global__ __launch_bounds__(256) void tgemm_k(const float* __restrict__ A,
                                               const float* __restrict__ Bm,
                                               float* __restrict__ C,
                                               int M, int Nn, int K,
                                               const float* __restrict__ freqs,
                                               int mode)
{
    __shared__ float As[2][128][20];
    __shared__ float Bs[2][16][136];

    int tid = threadIdx.x;
    int warp = tid >> 5, lane = tid & 31;
    int g = lane >> 2, tig = lane & 3;
    int wm = (warp >> 2) * 64;
    int wn = (warp & 3) * 32;

    int lrowA = lane & 15;
    int lcolA = (lane >> 4) << 2;

    int ar = tid >> 2;
    int ac = (tid & 3) * 4;
    int br = tid >> 4;
    int bc = (tid & 15) * 8;

    const float* Aq  = A + (size_t)(blockIdx.y * 128 + ar) * K + ac;
    const float* Aq2 = Aq + (size_t)64 * K;
    const float* Bq  = Bm + (size_t)br * Nn + blockIdx.x * 128 + bc;

    float acc[4][4][4];
    #pragma unroll
    for (int i = 0; i < 4; i++)
        #pragma unroll
        for (int j = 0; j < 4; j++)
            #pragma unroll
            for (int r = 0; r < 4; r++) acc[i][j][r] = 0.0f;

    cpa16(&As[0][ar][ac],      Aq);
    cpa16(&As[0][ar + 64][ac], Aq2);
    cpa16(&Bs[0][br][bc],      Bq);
    cpa16(&Bs[0][br][bc + 4],  Bq + 4);
    CP_COMMIT();

    int T = K / 16;
    for (int t = 0; t < T; t++) {
        int cur = t & 1;
        CP_WAIT(0);
        __syncthreads();

        if (t + 1 < T) {
            Aq += 16; Aq2 += 16; Bq += (size_t)16 * Nn;
            int nxt = cur ^ 1;
            cpa16(&As[nxt][ar][ac],      Aq);
            cpa16(&As[nxt][ar + 64][ac], Aq2);
            cpa16(&Bs[nxt][br][bc],      Bq);
            cpa16(&Bs[nxt][br][bc + 4],  Bq + 4);
            CP_COMMIT();
        }

        #pragma unroll
        for (int ks = 0; ks < 2; ks++) {
            int k0 = ks * 8;
            unsigned af[4][4], bf[4][2];
            #pragma unroll
            for (int mt = 0; mt < 4; mt++)
                ldsm4(af[mt][0], af[mt][1], af[mt][2], af[mt][3],
                      &As[cur][wm + mt * 16 + lrowA][k0 + lcolA]);
            #pragma unroll
            for (int nt = 0; nt < 4; nt++) {
                int cb = wn + nt * 8 + g;
                bf[nt][0] = f2u(Bs[cur][k0 + tig    ][cb]);
                bf[nt][1] = f2u(Bs[cur][k0 + tig + 4][cb]);
            }
            #pragma unroll
            for (int mt = 0; mt < 4; mt++)
                #pragma unroll
                for (int nt = 0; nt < 4; nt++)
                    mma_tf32(acc[mt][nt], af[mt], bf[nt][0], bf[nt][1]);
        }
    }

    int m0 = blockIdx.y * 128 + wm, n0 = blockIdx.x * 128 + wn;
    if (mode == 0) {
        #pragma unroll
        for (int mt = 0; mt < 4; mt++) {
            int row = m0 + mt * 16 + g;
            #pragma unroll
            for (int nt = 0; nt < 4; nt++) {
                int col = n0 + nt * 8 + 2 * tig;
                *(float2*)&C[(size_t)row * Nn + col]       = make_float2(acc[mt][nt][0], acc[mt][nt][1]);
                *(float2*)&C[(size_t)(row + 8) * Nn + col] = make_float2(acc[mt][nt][2], acc[mt][nt][3]);
            }
        }
    } else {
        #pragma unroll
        for (int mt = 0; mt < 4; mt++) {
            #pragma unroll
            for (int nt = 0; nt < 4; nt++) {
                int col = n0 + nt * 8 + 2 * tig;
                #pragma unroll
                for (int half = 0; half < 2; half++) {
                    int row = m0 + mt * 16 + g + half * 8;
                    float vx = acc[mt][nt][half * 2];
                    float vy = acc[mt][nt][half * 2 + 1];
                    if (col < 2048) {
                        int i = (col & 63) >> 1;
                        int pos = row & (SEQ - 1);
                        float f = (float)pos * freqs[i];
                        float sn, cs;
                        sincosf(f, &sn, &cs);
                        *(float2*)&C[(size_t)row * Nn + col] =
                            make_float2(tf32r(vx * cs - vy * sn),
                                        tf32r(vy * cs + vx * sn));
                    } else {
                        int hh = (col >> 6) & 15;
                        int d = col & 63;
                        int bb = row >> 11;
                        int key = row & (SEQ - 1);
                        size_t base = ((size_t)(bb * NHEADS + hh) * DH + d) * SEQ + key;
                        g_vt[base]       = tf32r(vx);
                        g_vt[base + SEQ] = tf32r(vy);
                    }
                }
            }
        }
    }
}

// ============================================================
// 3) Gates
// ============================================================
__global__ __launch_bounds__(256) void gates_k(const float* __restrict__ wg,
                                               const float* __restrict__ bg)
{
    int t = blockIdx.x;
    int tid = threadIdx.x;
    int h = tid & 15, chunk = tid >> 4;
    const float* xr = g_xn + (size_t)t * DIM;
    float acc = 0.0f;
    int d0 = chunk * 64;
    #pragma unroll 8
    for (int d = d0; d < d0 + 64; d++) acc += xr[d] * wg[d * NHEADS + h];

    __shared__ float s[16][16];
    s[chunk][h] = acc;
    __syncthreads();
    if (tid < 16) {
        float v = bg[tid];
        #pragma unroll
        for (int c = 0; c < 16; c++) v += s[c][tid];
        g_gate[t * NHEADS + tid] = 1.0f / (1.0f + expf(-v));
    }
}

// ============================================================
// 5) Flash attention tf32 MMA. BM=128, Q in regs, cp.async K/V,
//    LDSM K + LDSM V, P staged via warp-private smem -> LDSM.
// ============================================================
#define KSP 76
#define VTP 68
#define PSP 76
#define KBUF (64 * KSP)
#define VBUF (64 * VTP)
#define VOFF (2 * KBUF)
#define POFF (VOFF + 2 * VBUF)
#define ATTN_SMEM ((POFF + 8 * 16 * PSP) * 4)   // 112640 bytes
__global__ __launch_bounds__(256) void attn_k()
{
    extern __shared__ float sm[];

    int qt = blockIdx.x, h = blockIdx.y, b = blockIdx.z;
    int tid = threadIdx.x, warp = tid >> 5, lane = tid & 31;
    int g = lane >> 2, tig = lane & 3;
    int tBase = b * SEQ + qt * 128;
    int r0 = warp * 16;
    const float scale = 0.125f;

    int lrowB = (lane & 7) + ((lane & 16) >> 1);
    int lcolB = (lane & 8) >> 1;
    int lrowA = lane & 15;
    int lcolA = (lane >> 4) << 2;

    float* Pw = sm + POFF + warp * 16 * PSP;   // warp-private [16][76]

    int ldr = tid >> 4;
    int ldc = (tid & 15) << 2;

    const float* Kg = g_qkv + (size_t)(b * SEQ) * QKVC + 1024 + h * DH + ldc;
    const float* Vg = g_vt + ((size_t)(b * NHEADS + h) * DH) * SEQ + ldc;

    unsigned qf[8][4];
    {
        const float* q0 = g_qkv + (size_t)(tBase + r0 + g) * QKVC + h * DH;
        const float* q1 = q0 + (size_t)8 * QKVC;
        #pragma unroll
        for (int k8 = 0; k8 < 8; k8++) {
            int k0 = k8 * 8;
            qf[k8][0] = f2u(q0[k0 + tig]     * scale);
            qf[k8][1] = f2u(q1[k0 + tig]     * scale);
            qf[k8][2] = f2u(q0[k0 + tig + 4] * scale);
            qf[k8][3] = f2u(q1[k0 + tig + 4] * scale);
        }
    }

    float mrow0 = -INFINITY, mrow1 = -INFINITY, lrow0 = 0.0f, lrow1 = 0.0f;
    float o[8][4];
    #pragma unroll
    for (int nt = 0; nt < 8; nt++)
        #pragma unroll
        for (int r = 0; r < 4; r++) o[nt][r] = 0.0f;

    #pragma unroll
    for (int i = 0; i < 4; i++) {
        int r = ldr + i * 16;
        cpa16(&sm[r * KSP + ldc],        Kg + (size_t)r * QKVC);
        cpa16(&sm[VOFF + r * VTP + ldc], Vg + (size_t)r * SEQ);
    }
    CP_COMMIT();

    int T = SEQ / 64;
    for (int kt = 0; kt < T; kt++) {
        int cur = kt & 1;
        CP_WAIT(0);
        __syncthreads();

        if (kt + 1 < T) {
            int nxt = cur ^ 1;
            const float* Kn = Kg + (size_t)(kt + 1) * 64 * QKVC;
            const float* Vn = Vg + (kt + 1) * 64;
            #pragma unroll
            for (int i = 0; i < 4; i++) {
                int r = ldr + i * 16;
                cpa16(&sm[nxt * KBUF + r * KSP + ldc],        Kn + (size_t)r * QKVC);
                cpa16(&sm[VOFF + nxt * VBUF + r * VTP + ldc], Vn + (size_t)r * SEQ);
            }
            CP_COMMIT();
        }

        const float* Kb = sm + cur * KBUF;
        const float* Vb = sm + VOFF + cur * VBUF;

        // ---- S = Q K^T ----
        float s[8][4];
        #pragma unroll
        for (int nt = 0; nt < 8; nt++)
            #pragma unroll
            for (int r = 0; r < 4; r++) s[nt][r] = 0.0f;

        #pragma unroll
        for (int k8 = 0; k8 < 8; k8++) {
            int k0 = k8 * 8;
            #pragma unroll
            for (int ntp = 0; ntp < 4; ntp++) {
                unsigned b0a, b1a, b0b, b1b;
                ldsm4(b0a, b1a, b0b, b1b, &Kb[(ntp * 16 + lrowB) * KSP + k0 + lcolB]);
                mma_tf32(s[2 * ntp],     qf[k8], b0a, b1a);
                mma_tf32(s[2 * ntp + 1], qf[k8], b0b, b1b);
            }
        }

        // ---- online softmax ----
        float mx0 = -INFINITY, mx1 = -INFINITY;
        #pragma unroll
        for (int nt = 0; nt < 8; nt++) {
            mx0 = fmaxf(mx0, fmaxf(s[nt][0], s[nt][1]));
            mx1 = fmaxf(mx1, fmaxf(s[nt][2], s[nt][3]));
        }
        mx0 = fmaxf(mx0, __shfl_xor_sync(0xFFFFFFFFu, mx0, 1));
        mx0 = fmaxf(mx0, __shfl_xor_sync(0xFFFFFFFFu, mx0, 2));
        mx1 = fmaxf(mx1, __shfl_xor_sync(0xFFFFFFFFu, mx1, 1));
        mx1 = fmaxf(mx1, __shfl_xor_sync(0xFFFFFFFFu, mx1, 2));

        float mn0 = fmaxf(mrow0, mx0), mn1 = fmaxf(mrow1, mx1);
        float corr0 = __expf(mrow0 - mn0), corr1 = __expf(mrow1 - mn1);
        float rs0 = 0.0f, rs1 = 0.0f;
        #pragma unroll
        for (int nt = 0; nt < 8; nt++) {
            s[nt][0] = __expf(s[nt][0] - mn0);
            s[nt][1] = __expf(s[nt][1] - mn0);
            s[nt][2] = __expf(s[nt][2] - mn1);
            s[nt][3] = __expf(s[nt][3] - mn1);
            rs0 += s[nt][0] + s[nt][1];
            rs1 += s[nt][2] + s[nt][3];
        }
        rs0 += __shfl_xor_sync(0xFFFFFFFFu, rs0, 1);
        rs0 += __shfl_xor_sync(0xFFFFFFFFu, rs0, 2);
        rs1 += __shfl_xor_sync(0xFFFFFFFFu, rs1, 1);
        rs1 += __shfl_xor_sync(0xFFFFFFFFu, rs1, 2);
        lrow0 = lrow0 * corr0 + rs0;  mrow0 = mn0;
        lrow1 = lrow1 * corr1 + rs1;  mrow1 = mn1;
        #pragma unroll
        for (int nt = 0; nt < 8; nt++) {
            o[nt][0] *= corr0; o[nt][1] *= corr0;
            o[nt][2] *= corr1; o[nt][3] *= corr1;
        }

        // ---- stage P (tf32) into warp-private smem ----
        __syncwarp();
        #pragma unroll
        for (int nt = 0; nt < 8; nt++) {
            *(float2*)&Pw[g * PSP + nt * 8 + 2 * tig] =
                make_float2(tf32r(s[nt][0]), tf32r(s[nt][1]));
            *(float2*)&Pw[(g + 8) * PSP + nt * 8 + 2 * tig] =
                make_float2(tf32r(s[nt][2]), tf32r(s[nt][3]));
        }
        __syncwarp();

        // ---- O += P V : P A-fragments + V B-fragments via LDSM ----
        #pragma unroll
        for (int kv = 0; kv < 8; kv++) {
            unsigned pf[4];
            ldsm4(pf[0], pf[1], pf[2], pf[3], &Pw[lrowA * PSP + kv * 8 + lcolA]);
            #pragma unroll
            for (int ntp = 0; ntp < 4; ntp++) {
                unsigned b0a, b1a, b0b, b1b;
                ldsm4(b0a, b1a, b0b, b1b, &Vb[(ntp * 16 + lrowB) * VTP + kv * 8 + lcolB]);
                mma_tf32(o[2 * ntp],     pf, b0a, b1a);
                mma_tf32(o[2 * ntp + 1], pf, b0b, b1b);
            }
        }
    }

    // ---- epilogue ----
    int row0 = tBase + r0 + g;
    float sc0 = (1.0f / lrow0) * g_gate[row0 * NHEADS + h];
    float sc1 = (1.0f / lrow1) * g_gate[(row0 + 8) * NHEADS + h];
    #pragma unroll
    for (int nt = 0; nt < 8; nt++) {
        int col = h * DH + nt * 8 + 2 * tig;
        *(float2*)&g_att[(size_t)row0 * DIM + col] =
            make_float2(tf32r(o[nt][0] * sc0), tf32r(o[nt][1] * sc0));
        *(float2*)&g_att[(size_t)(row0 + 8) * DIM + col] =
            make_float2(tf32r(o[nt][2] * sc1), tf32r(o[nt][3] * sc1));
    }
}

// ============================================================
// launcher — two-stream DAG (fork/join via events)
// ============================================================
extern "C" void kernel_launch(void* const* d_in, const int* in_sizes, int n_in,
                              void* d_out, int out_size)
{
    const float* x       = (const float*)d_in[0];
    const float* gamma   = (const float*)d_in[1];
    const float* w_qkv   = (const float*)d_in[2];
    const float* w_gates = (const float*)d_in[3];
    const float* b_gates = (const float*)d_in[4];
    const float* w_out   = (const float*)d_in[5];
    const float* freqs   = (const float*)d_in[6];
    float* out = (float*)d_out;

    float *xn_p, *qkv_p, *att_p, *wqkvt_p, *woutt_p;
    cudaGetSymbolAddress((void**)&xn_p,    g_xn);
    cudaGetSymbolAddress((void**)&qkv_p,   g_qkv);
    cudaGetSymbolAddress((void**)&att_p,   g_att);
    cudaGetSymbolAddress((void**)&wqkvt_p, g_wqkvt);
    cudaGetSymbolAddress((void**)&woutt_p, g_woutt);

    cudaFuncSetAttribute(attn_k, cudaFuncAttributeMaxDynamicSharedMemorySize, ATTN_SMEM);

    static cudaStream_t s2 = nullptr;
    static cudaEvent_t e0 = nullptr, eR = nullptr, eX = nullptr, eG = nullptr;
    if (!s2) {
        cudaStreamCreateWithFlags(&s2, cudaStreamNonBlocking);
        cudaEventCreateWithFlags(&e0, cudaEventDisableTiming);
        cudaEventCreateWithFlags(&eR, cudaEventDisableTiming);
        cudaEventCreateWithFlags(&eX, cudaEventDisableTiming);
        cudaEventCreateWithFlags(&eG, cudaEventDisableTiming);
    }

    cudaEventRecord(e0, 0);
    cudaStreamWaitEvent(s2, e0, 0);
    round_k<<<(DIM * QKVC) / 1024, 256, 0, s2>>>(w_qkv, wqkvt_p);
    round_k<<<(DIM * DIM)  / 1024, 256, 0, s2>>>(w_out, woutt_p);
    cudaEventRecord(eR, s2);

    rmsnorm_k<<<NTOK, 256>>>(x, gamma);
    cudaEventRecord(eX, 0);

    cudaStreamWaitEvent(s2, eX, 0);
    gates_k<<<NTOK, 256, 0, s2>>>(w_gates, b_gates);
    cudaEventRecord(eG, s2);

    cudaStreamWaitEvent(0, eR, 0);
    tgemm_k<<<dim3(QKVC / 128, NTOK / 128), 256>>>(xn_p, wqkvt_p, qkv_p,
                                                   NTOK, QKVC, DIM, freqs, 1);

    cudaStreamWaitEvent(0, eG, 0);
    attn_k<<<dim3(SEQ / 128, NHEADS, BATCH), 256, ATTN_SMEM>>>();
    tgemm_k<<<dim3(DIM / 128, NTOK / 128), 256>>>(att_p, woutt_p, out,
                                                  NTOK, DIM, DIM, freqs, 0);
}